// round 1
// baseline (speedup 1.0000x reference)
#include <cuda_runtime.h>
#include <cstdint>

#define NODES_TOTAL 100000
#define NNODES      20000
#define TN          50
#define INF         256
#define HIDF        256
#define OUTF        256
#define CATF        512

// Scratch (static __device__ arrays: allocation-free per harness rules)
__device__ __align__(16) float g_qh[(size_t)NODES_TOTAL * HIDF];   // 102.4 MB
__device__ __align__(16) float g_cat[(size_t)NNODES * CATF];       // 41 MB

// ---------------------------------------------------------------------------
// helpers
// ---------------------------------------------------------------------------
__device__ __forceinline__ uint32_t f2tf32(float x) {
    uint32_t r;
    asm("cvt.rna.tf32.f32 %0, %1;" : "=r"(r) : "f"(x));
    return r;
}

__device__ __forceinline__ void mma_tf32(float c[4],
                                         uint32_t a0, uint32_t a1, uint32_t a2, uint32_t a3,
                                         uint32_t b0, uint32_t b1) {
    asm volatile("mma.sync.aligned.m16n8k8.row.col.f32.tf32.tf32.f32 "
                 "{%0,%1,%2,%3}, {%4,%5,%6,%7}, {%8,%9}, {%0,%1,%2,%3};"
                 : "+f"(c[0]), "+f"(c[1]), "+f"(c[2]), "+f"(c[3])
                 : "r"(a0), "r"(a1), "r"(a2), "r"(a3), "r"(b0), "r"(b1));
}

__device__ __forceinline__ void cp_async16(void* smem_dst, const void* gmem_src, bool pred) {
    uint32_t saddr = (uint32_t)__cvta_generic_to_shared(smem_dst);
    int sz = pred ? 16 : 0;
    asm volatile("cp.async.cg.shared.global [%0], [%1], 16, %2;"
                 :: "r"(saddr), "l"(gmem_src), "r"(sz));
}

// ---------------------------------------------------------------------------
// Generic TF32 GEMM:  C[m, 0..255] = relu( sum_k A[m,k]*B[n,k] + bias[n] )
// A: [M, K] row-major fp32, B: [256, K] row-major fp32 (torch weight layout)
// CTA tile 128x128, K-tile 16, cp.async double buffer. Grid: (ceil(M/128), 2)
// ---------------------------------------------------------------------------
#define KT   16
#define SROW 20   // padded smem row (floats): conflict-free mma reads, 16B-aligned stores

__global__ __launch_bounds__(256) void gemm_relu_kernel(
    const float* __restrict__ A, const float* __restrict__ B,
    const float* __restrict__ bias, float* __restrict__ C,
    int M, int K)
{
    __shared__ float As[2][128 * SROW];
    __shared__ float Bs[2][128 * SROW];

    const int tid  = threadIdx.x;
    const int m0   = blockIdx.x * 128;
    const int n0   = blockIdx.y * 128;
    const int warp = tid >> 5;
    const int lane = tid & 31;
    const int g    = lane >> 2;   // groupID 0..7
    const int tg   = lane & 3;    // threadID in group 0..3
    const int wm   = (warp >> 2) * 64;  // warp M offset in tile
    const int wn   = (warp & 3) * 32;   // warp N offset in tile

    float acc[4][4][4];
    #pragma unroll
    for (int i = 0; i < 4; i++)
        #pragma unroll
        for (int j = 0; j < 4; j++)
            #pragma unroll
            for (int r = 0; r < 4; r++) acc[i][j][r] = 0.f;

    const int NT = K / KT;

    // per-thread load slots: 2 float4 for A, 2 for B per k-tile
    // f4 index i in {tid, tid+256}: row = i>>2 (0..127), c4 = i&3 (0..3)
    const int row0 = tid >> 2, c40 = (tid & 3) * 4;
    const int row1 = (tid + 256) >> 2, c41 = ((tid + 256) & 3) * 4;

    // prefetch tile 0
    {
        const int kk = 0;
        cp_async16(&As[0][row0 * SROW + c40], A + (size_t)(m0 + row0) * K + kk + c40, (m0 + row0) < M);
        cp_async16(&As[0][row1 * SROW + c41], A + (size_t)(m0 + row1) * K + kk + c41, (m0 + row1) < M);
        cp_async16(&Bs[0][row0 * SROW + c40], B + (size_t)(n0 + row0) * K + kk + c40, true);
        cp_async16(&Bs[0][row1 * SROW + c41], B + (size_t)(n0 + row1) * K + kk + c41, true);
        asm volatile("cp.async.commit_group;");
    }

    for (int kt = 0; kt < NT; kt++) {
        const int buf = kt & 1;
        if (kt + 1 < NT) {
            const int nb_ = (kt + 1) & 1;
            const int kk = (kt + 1) * KT;
            cp_async16(&As[nb_][row0 * SROW + c40], A + (size_t)(m0 + row0) * K + kk + c40, (m0 + row0) < M);
            cp_async16(&As[nb_][row1 * SROW + c41], A + (size_t)(m0 + row1) * K + kk + c41, (m0 + row1) < M);
            cp_async16(&Bs[nb_][row0 * SROW + c40], B + (size_t)(n0 + row0) * K + kk + c40, true);
            cp_async16(&Bs[nb_][row1 * SROW + c41], B + (size_t)(n0 + row1) * K + kk + c41, true);
            asm volatile("cp.async.commit_group;");
            asm volatile("cp.async.wait_group 1;");
        } else {
            asm volatile("cp.async.wait_group 0;");
        }
        __syncthreads();

        #pragma unroll
        for (int ks = 0; ks < 2; ks++) {
            const int k = ks * 8 + tg;
            uint32_t af[4][4];
            #pragma unroll
            for (int mf = 0; mf < 4; mf++) {
                const int rb = wm + mf * 16;
                af[mf][0] = f2tf32(As[buf][(rb + g)     * SROW + k]);
                af[mf][1] = f2tf32(As[buf][(rb + g + 8) * SROW + k]);
                af[mf][2] = f2tf32(As[buf][(rb + g)     * SROW + k + 4]);
                af[mf][3] = f2tf32(As[buf][(rb + g + 8) * SROW + k + 4]);
            }
            uint32_t bfr[4][2];
            #pragma unroll
            for (int nf = 0; nf < 4; nf++) {
                const int nb2 = wn + nf * 8;
                bfr[nf][0] = f2tf32(Bs[buf][(nb2 + g) * SROW + k]);
                bfr[nf][1] = f2tf32(Bs[buf][(nb2 + g) * SROW + k + 4]);
            }
            #pragma unroll
            for (int mf = 0; mf < 4; mf++)
                #pragma unroll
                for (int nf = 0; nf < 4; nf++)
                    mma_tf32(acc[mf][nf], af[mf][0], af[mf][1], af[mf][2], af[mf][3],
                             bfr[nf][0], bfr[nf][1]);
        }
        __syncthreads();
    }

    // epilogue: bias + relu, store fp32 (C row stride fixed at 256)
    #pragma unroll
    for (int mf = 0; mf < 4; mf++) {
        const int r0 = m0 + wm + mf * 16 + g;
        #pragma unroll
        for (int nf = 0; nf < 4; nf++) {
            const int c0 = n0 + wn + nf * 8 + tg * 2;
            const float b0 = __ldg(&bias[c0]);
            const float b1 = __ldg(&bias[c0 + 1]);
            if (r0 < M) {
                float2 v = make_float2(fmaxf(acc[mf][nf][0] + b0, 0.f),
                                       fmaxf(acc[mf][nf][1] + b1, 0.f));
                *(float2*)&C[(size_t)r0 * 256 + c0] = v;
            }
            if (r0 + 8 < M) {
                float2 v = make_float2(fmaxf(acc[mf][nf][2] + b0, 0.f),
                                       fmaxf(acc[mf][nf][3] + b1, 0.f));
                *(float2*)&C[(size_t)(r0 + 8) * 256 + c0] = v;
            }
        }
    }
}

// ---------------------------------------------------------------------------
// Aggregation: h_agg[n] = sum_t w[n,t]*QH[nb[n,t]] / sum_t w[n,t]
// writes g_cat[n] = [ h[nodeset[n]] (256) | h_agg[n] (256) ]
// 64 threads per node (float4/lane), 4 nodes per 256-thread block
// ---------------------------------------------------------------------------
__global__ __launch_bounds__(256) void agg_kernel(
    const float* __restrict__ h, const int* __restrict__ nodeset,
    const int* __restrict__ nb_nodes, const float* __restrict__ nb_w)
{
    __shared__ int   s_idx[4][TN];
    __shared__ float s_w[4][TN];

    const int tid = threadIdx.x;
    const int grp = tid >> 6;       // 0..3
    const int l   = tid & 63;       // 0..63
    const int n   = blockIdx.x * 4 + grp;   // 20000/4 = 5000 blocks exact

    if (l < TN) {
        s_idx[grp][l] = nb_nodes[n * TN + l];
        s_w[grp][l]   = nb_w[n * TN + l];
    }
    __syncthreads();

    float wsum = 0.f;
    #pragma unroll
    for (int t = 0; t < TN; t++) wsum += s_w[grp][t];   // smem broadcast

    const int col = l * 4;
    float4 acc = make_float4(0.f, 0.f, 0.f, 0.f);
    #pragma unroll 5
    for (int t = 0; t < TN; t++) {
        const int   idx = s_idx[grp][t];
        const float w   = s_w[grp][t];
        const float4 v  = *(const float4*)&g_qh[(size_t)idx * HIDF + col];
        acc.x += w * v.x; acc.y += w * v.y; acc.z += w * v.z; acc.w += w * v.w;
    }
    const float inv = 1.f / wsum;
    acc.x *= inv; acc.y *= inv; acc.z *= inv; acc.w *= inv;
    *(float4*)&g_cat[(size_t)n * CATF + INF + col] = acc;

    // self-feature copy into the first half of the concat row
    const int self = nodeset[n];
    *(float4*)&g_cat[(size_t)n * CATF + col] =
        *(const float4*)&h[(size_t)self * INF + col];
}

// ---------------------------------------------------------------------------
// In-place row L2 normalize of d_out [20000, 256]; one warp per row
// ---------------------------------------------------------------------------
__global__ __launch_bounds__(256) void norm_kernel(float* __restrict__ out)
{
    const int gwarp = (blockIdx.x * blockDim.x + threadIdx.x) >> 5;
    const int lane  = threadIdx.x & 31;
    if (gwarp >= NNODES) return;
    float* row = out + (size_t)gwarp * OUTF;

    float4 v0 = *(float4*)&row[lane * 4];
    float4 v1 = *(float4*)&row[128 + lane * 4];
    float ss = v0.x * v0.x + v0.y * v0.y + v0.z * v0.z + v0.w * v0.w
             + v1.x * v1.x + v1.y * v1.y + v1.z * v1.z + v1.w * v1.w;
    #pragma unroll
    for (int o = 16; o; o >>= 1) ss += __shfl_xor_sync(0xffffffffu, ss, o);
    const float inv = rsqrtf(ss);
    v0.x *= inv; v0.y *= inv; v0.z *= inv; v0.w *= inv;
    v1.x *= inv; v1.y *= inv; v1.z *= inv; v1.w *= inv;
    *(float4*)&row[lane * 4]       = v0;
    *(float4*)&row[128 + lane * 4] = v1;
}

// ---------------------------------------------------------------------------
extern "C" void kernel_launch(void* const* d_in, const int* in_sizes, int n_in,
                              void* d_out, int out_size)
{
    const float* h        = (const float*)d_in[0];
    const int*   nodeset  = (const int*)d_in[1];
    const int*   nb_nodes = (const int*)d_in[2];
    const float* nb_w     = (const float*)d_in[3];
    const float* Qw       = (const float*)d_in[4];
    const float* Qb       = (const float*)d_in[5];
    const float* Ww       = (const float*)d_in[6];
    const float* Wb       = (const float*)d_in[7];
    float*       out      = (float*)d_out;

    float* qh  = nullptr;
    float* cat = nullptr;
    cudaGetSymbolAddress((void**)&qh,  g_qh);
    cudaGetSymbolAddress((void**)&cat, g_cat);

    // 1) QH = relu(h @ Qw^T + Qb)   [100000, 256], K=256
    {
        dim3 grid((NODES_TOTAL + 127) / 128, 2);
        gemm_relu_kernel<<<grid, 256>>>(h, Qw, Qb, qh, NODES_TOTAL, INF);
    }
    // 2) aggregate + self gather -> g_cat [20000, 512]
    agg_kernel<<<NNODES / 4, 256>>>(h, nodeset, nb_nodes, nb_w);

    // 3) out = relu(g_cat @ Ww^T + Wb)  [20000, 256], K=512
    {
        dim3 grid((NNODES + 127) / 128, 2);
        gemm_relu_kernel<<<grid, 256>>>(cat, Ww, Wb, out, NNODES, CATF);
    }
    // 4) in-place L2 normalize
    norm_kernel<<<(NNODES * 32 + 255) / 256, 256>>>(out);
}

// round 2
// speedup vs baseline: 1.1582x; 1.1582x over previous
#include <cuda_runtime.h>
#include <cuda_bf16.h>
#include <cstdint>

#define NODES_TOTAL 100000
#define NNODES      20000
#define TN          50
#define INF         256
#define HIDF        256
#define OUTF        256
#define CATF        512

// Scratch (static __device__ arrays: allocation-free per harness rules)
__device__ __align__(16) __nv_bfloat16 g_qh[(size_t)NODES_TOTAL * HIDF]; // 51.2 MB (L2-resident)
__device__ __align__(16) float         g_cat[(size_t)NNODES * CATF];     // 41 MB

// ---------------------------------------------------------------------------
// helpers
// ---------------------------------------------------------------------------
__device__ __forceinline__ uint32_t f2tf32(float x) {
    uint32_t r;
    asm("cvt.rna.tf32.f32 %0, %1;" : "=r"(r) : "f"(x));
    return r;
}

__device__ __forceinline__ void mma_tf32(float c[4],
                                         uint32_t a0, uint32_t a1, uint32_t a2, uint32_t a3,
                                         uint32_t b0, uint32_t b1) {
    asm volatile("mma.sync.aligned.m16n8k8.row.col.f32.tf32.tf32.f32 "
                 "{%0,%1,%2,%3}, {%4,%5,%6,%7}, {%8,%9}, {%0,%1,%2,%3};"
                 : "+f"(c[0]), "+f"(c[1]), "+f"(c[2]), "+f"(c[3])
                 : "r"(a0), "r"(a1), "r"(a2), "r"(a3), "r"(b0), "r"(b1));
}

__device__ __forceinline__ void cp_async16(void* smem_dst, const void* gmem_src, bool pred) {
    uint32_t saddr = (uint32_t)__cvta_generic_to_shared(smem_dst);
    int sz = pred ? 16 : 0;
    asm volatile("cp.async.cg.shared.global [%0], [%1], 16, %2;"
                 :: "r"(saddr), "l"(gmem_src), "r"(sz));
}

// ---------------------------------------------------------------------------
// Generic TF32 GEMM:  C[m, 0..255] = relu( sum_k A[m,k]*B[n,k] + bias[n] )
// A: [M, K] row-major fp32, B: [256, K] row-major fp32 (torch weight layout)
// CTA tile 128x128, K-tile 16, cp.async double buffer.
// Grid: (2 colTiles [x], rowTiles [y]) so both N-tiles of a row slab are
// launch-adjacent -> A rows are L2-hot on the second tile (halves A DRAM).
// ---------------------------------------------------------------------------
#define KT   16
#define SROW 20   // padded smem row (floats): conflict-free mma reads, 16B-aligned stores

template <bool BF16OUT>
__global__ __launch_bounds__(256) void gemm_relu_kernel(
    const float* __restrict__ A, const float* __restrict__ B,
    const float* __restrict__ bias, void* __restrict__ Cv,
    int M, int K)
{
    __shared__ float As[2][128 * SROW];
    __shared__ float Bs[2][128 * SROW];

    const int tid  = threadIdx.x;
    const int m0   = blockIdx.y * 128;
    const int n0   = blockIdx.x * 128;
    const int warp = tid >> 5;
    const int lane = tid & 31;
    const int g    = lane >> 2;   // groupID 0..7
    const int tg   = lane & 3;    // threadID in group 0..3
    const int wm   = (warp >> 2) * 64;  // warp M offset in tile
    const int wn   = (warp & 3) * 32;   // warp N offset in tile

    float acc[4][4][4];
    #pragma unroll
    for (int i = 0; i < 4; i++)
        #pragma unroll
        for (int j = 0; j < 4; j++)
            #pragma unroll
            for (int r = 0; r < 4; r++) acc[i][j][r] = 0.f;

    const int NT = K / KT;

    // per-thread load slots: 2 float4 for A, 2 for B per k-tile
    const int row0 = tid >> 2, c40 = (tid & 3) * 4;
    const int row1 = (tid + 256) >> 2, c41 = ((tid + 256) & 3) * 4;

    // prefetch tile 0
    {
        cp_async16(&As[0][row0 * SROW + c40], A + (size_t)(m0 + row0) * K + c40, (m0 + row0) < M);
        cp_async16(&As[0][row1 * SROW + c41], A + (size_t)(m0 + row1) * K + c41, (m0 + row1) < M);
        cp_async16(&Bs[0][row0 * SROW + c40], B + (size_t)(n0 + row0) * K + c40, true);
        cp_async16(&Bs[0][row1 * SROW + c41], B + (size_t)(n0 + row1) * K + c41, true);
        asm volatile("cp.async.commit_group;");
    }

    for (int kt = 0; kt < NT; kt++) {
        const int buf = kt & 1;
        if (kt + 1 < NT) {
            const int nb_ = (kt + 1) & 1;
            const int kk = (kt + 1) * KT;
            cp_async16(&As[nb_][row0 * SROW + c40], A + (size_t)(m0 + row0) * K + kk + c40, (m0 + row0) < M);
            cp_async16(&As[nb_][row1 * SROW + c41], A + (size_t)(m0 + row1) * K + kk + c41, (m0 + row1) < M);
            cp_async16(&Bs[nb_][row0 * SROW + c40], B + (size_t)(n0 + row0) * K + kk + c40, true);
            cp_async16(&Bs[nb_][row1 * SROW + c41], B + (size_t)(n0 + row1) * K + kk + c41, true);
            asm volatile("cp.async.commit_group;");
            asm volatile("cp.async.wait_group 1;");
        } else {
            asm volatile("cp.async.wait_group 0;");
        }
        __syncthreads();

        #pragma unroll
        for (int ks = 0; ks < 2; ks++) {
            const int k = ks * 8 + tg;
            uint32_t af[4][4];
            #pragma unroll
            for (int mf = 0; mf < 4; mf++) {
                const int rb = wm + mf * 16;
                af[mf][0] = f2tf32(As[buf][(rb + g)     * SROW + k]);
                af[mf][1] = f2tf32(As[buf][(rb + g + 8) * SROW + k]);
                af[mf][2] = f2tf32(As[buf][(rb + g)     * SROW + k + 4]);
                af[mf][3] = f2tf32(As[buf][(rb + g + 8) * SROW + k + 4]);
            }
            uint32_t bfr[4][2];
            #pragma unroll
            for (int nf = 0; nf < 4; nf++) {
                const int nb2 = wn + nf * 8;
                bfr[nf][0] = f2tf32(Bs[buf][(nb2 + g) * SROW + k]);
                bfr[nf][1] = f2tf32(Bs[buf][(nb2 + g) * SROW + k + 4]);
            }
            #pragma unroll
            for (int mf = 0; mf < 4; mf++)
                #pragma unroll
                for (int nf = 0; nf < 4; nf++)
                    mma_tf32(acc[mf][nf], af[mf][0], af[mf][1], af[mf][2], af[mf][3],
                             bfr[nf][0], bfr[nf][1]);
        }
        __syncthreads();
    }

    // epilogue: bias + relu, store (C row stride fixed at 256 elements)
    #pragma unroll
    for (int mf = 0; mf < 4; mf++) {
        const int r0 = m0 + wm + mf * 16 + g;
        #pragma unroll
        for (int nf = 0; nf < 4; nf++) {
            const int c0 = n0 + wn + nf * 8 + tg * 2;
            const float b0 = __ldg(&bias[c0]);
            const float b1 = __ldg(&bias[c0 + 1]);
            #pragma unroll
            for (int half = 0; half < 2; half++) {
                const int r = r0 + half * 8;
                if (r < M) {
                    float v0 = fmaxf(acc[mf][nf][half * 2 + 0] + b0, 0.f);
                    float v1 = fmaxf(acc[mf][nf][half * 2 + 1] + b1, 0.f);
                    if (BF16OUT) {
                        __nv_bfloat162 p = __float22bfloat162_rn(make_float2(v0, v1));
                        *(__nv_bfloat162*)((__nv_bfloat16*)Cv + (size_t)r * 256 + c0) = p;
                    } else {
                        *(float2*)((float*)Cv + (size_t)r * 256 + c0) = make_float2(v0, v1);
                    }
                }
            }
        }
    }
}

// ---------------------------------------------------------------------------
// Aggregation: h_agg[n] = sum_t w[n,t]*QH[nb[n,t]] / sum_t w[n,t]
// QH is bf16 [100000, 256] (L2-resident). One warp per node: each lane owns
// 8 columns (one 16B bf16 load per neighbor). Also copies h[nodeset[n]] into
// the first half of the concat row.
// ---------------------------------------------------------------------------
__global__ __launch_bounds__(256) void agg_kernel(
    const float* __restrict__ h, const int* __restrict__ nodeset,
    const int* __restrict__ nb_nodes, const float* __restrict__ nb_w)
{
    __shared__ int   s_idx[8][TN];
    __shared__ float s_w[8][TN];

    const int tid  = threadIdx.x;
    const int warp = tid >> 5;
    const int lane = tid & 31;
    const int n    = blockIdx.x * 8 + warp;   // 20000/8 = 2500 blocks exact

    for (int j = lane; j < TN; j += 32) {
        s_idx[warp][j] = nb_nodes[n * TN + j];
        s_w[warp][j]   = nb_w[n * TN + j];
    }
    __syncwarp();

    float wsum = 0.f;
    #pragma unroll
    for (int t = 0; t < TN; t++) wsum += s_w[warp][t];   // smem broadcast

    const int colb = lane * 8;   // bf16 column base for this lane
    float acc[8];
    #pragma unroll
    for (int i = 0; i < 8; i++) acc[i] = 0.f;

    #pragma unroll 5
    for (int t = 0; t < TN; t++) {
        const int   idx = s_idx[warp][t];
        const float w   = s_w[warp][t];
        const uint4 q   = *(const uint4*)(g_qh + (size_t)idx * HIDF + colb);
        const uint32_t u[4] = {q.x, q.y, q.z, q.w};
        #pragma unroll
        for (int i = 0; i < 4; i++) {
            const float lo = __uint_as_float(u[i] << 16);
            const float hi = __uint_as_float(u[i] & 0xffff0000u);
            acc[2 * i]     += w * lo;
            acc[2 * i + 1] += w * hi;
        }
    }
    const float inv = 1.f / wsum;
    float4 o0 = make_float4(acc[0] * inv, acc[1] * inv, acc[2] * inv, acc[3] * inv);
    float4 o1 = make_float4(acc[4] * inv, acc[5] * inv, acc[6] * inv, acc[7] * inv);
    float* dst = g_cat + (size_t)n * CATF + INF + colb;
    *(float4*)(dst)     = o0;
    *(float4*)(dst + 4) = o1;

    // self-feature copy into the first half of the concat row (8 floats/lane)
    const int self = nodeset[n];
    const float4* src = (const float4*)(h + (size_t)self * INF);
    float4* sdst = (float4*)(g_cat + (size_t)n * CATF);
    sdst[lane * 2]     = src[lane * 2];
    sdst[lane * 2 + 1] = src[lane * 2 + 1];
}

// ---------------------------------------------------------------------------
// In-place row L2 normalize of d_out [20000, 256]; one warp per row
// ---------------------------------------------------------------------------
__global__ __launch_bounds__(256) void norm_kernel(float* __restrict__ out)
{
    const int gwarp = (blockIdx.x * blockDim.x + threadIdx.x) >> 5;
    const int lane  = threadIdx.x & 31;
    if (gwarp >= NNODES) return;
    float* row = out + (size_t)gwarp * OUTF;

    float4 v0 = *(float4*)&row[lane * 4];
    float4 v1 = *(float4*)&row[128 + lane * 4];
    float ss = v0.x * v0.x + v0.y * v0.y + v0.z * v0.z + v0.w * v0.w
             + v1.x * v1.x + v1.y * v1.y + v1.z * v1.z + v1.w * v1.w;
    #pragma unroll
    for (int o = 16; o; o >>= 1) ss += __shfl_xor_sync(0xffffffffu, ss, o);
    const float inv = rsqrtf(ss);
    v0.x *= inv; v0.y *= inv; v0.z *= inv; v0.w *= inv;
    v1.x *= inv; v1.y *= inv; v1.z *= inv; v1.w *= inv;
    *(float4*)&row[lane * 4]       = v0;
    *(float4*)&row[128 + lane * 4] = v1;
}

// ---------------------------------------------------------------------------
extern "C" void kernel_launch(void* const* d_in, const int* in_sizes, int n_in,
                              void* d_out, int out_size)
{
    const float* h        = (const float*)d_in[0];
    const int*   nodeset  = (const int*)d_in[1];
    const int*   nb_nodes = (const int*)d_in[2];
    const float* nb_w     = (const float*)d_in[3];
    const float* Qw       = (const float*)d_in[4];
    const float* Qb       = (const float*)d_in[5];
    const float* Ww       = (const float*)d_in[6];
    const float* Wb       = (const float*)d_in[7];
    float*       out      = (float*)d_out;

    __nv_bfloat16* qh = nullptr;
    float*         cat = nullptr;
    cudaGetSymbolAddress((void**)&qh,  g_qh);
    cudaGetSymbolAddress((void**)&cat, g_cat);

    // 1) QH = relu(h @ Qw^T + Qb) -> bf16 [100000, 256], K=256
    {
        dim3 grid(2, (NODES_TOTAL + 127) / 128);
        gemm_relu_kernel<true><<<grid, 256>>>(h, Qw, Qb, qh, NODES_TOTAL, INF);
    }
    // 2) aggregate + self gather -> g_cat [20000, 512]
    agg_kernel<<<NNODES / 8, 256>>>(h, nodeset, nb_nodes, nb_w);

    // 3) out = relu(g_cat @ Ww^T + Wb)  [20000, 256], K=512
    {
        dim3 grid(2, (NNODES + 127) / 128);
        gemm_relu_kernel<false><<<grid, 256>>>(cat, Ww, Wb, out, NNODES, CATF);
    }
    // 4) in-place L2 normalize
    norm_kernel<<<(NNODES * 32 + 255) / 256, 256>>>(out);
}